// round 7
// baseline (speedup 1.0000x reference)
#include <cuda_runtime.h>
#include <cuda_bf16.h>
#include <cstdint>
#include <math.h>

// ---------------- problem constants ----------------
#define NB     2
#define TT     2048
#define BT     4096      // NB*TT tokens
#define DM     2048
#define NH     16
#define DH     128
#define CH     144       // NH + DH
#define RQ     6
#define RKV    4
#define NQ     864       // RQ*CH
#define NKV    576       // RKV*CH

// ---------------- scratch (device globals; no allocs allowed) ----------------
__device__ float g_abq [BT * NQ];
__device__ float g_abkv[BT * NKV];

// bf16 hi/lo split scratch
__device__ __nv_bfloat16 g_xh [BT * DM],  g_xl [BT * DM];
__device__ __nv_bfloat16 g_wqh[NQ * DM],  g_wql[NQ * DM];
__device__ __nv_bfloat16 g_wkh[NKV * DM], g_wkl[NKV * DM];
__device__ __nv_bfloat16 g_woh[DM * DM],  g_wol[DM * DM];
__device__ __nv_bfloat16 g_yh [BT * DM],  g_yl [BT * DM];

// q/k/v bf16 hi/lo, layout [b,h,t,d]
#define QKV_ELEMS (NB * NH * TT * DH)
__device__ __nv_bfloat16 g_qh[QKV_ELEMS], g_ql[QKV_ELEMS];
__device__ __nv_bfloat16 g_kh[QKV_ELEMS], g_kl[QKV_ELEMS];
__device__ __nv_bfloat16 g_vh[QKV_ELEMS], g_vl[QKV_ELEMS];

// ================= helpers =================
__device__ __forceinline__ uint32_t smem_u32(const void* p) {
    uint32_t a;
    asm("{ .reg .u64 t; cvta.to.shared.u64 t, %1; cvt.u32.u64 %0, t; }" : "=r"(a) : "l"(p));
    return a;
}
#define SWZ(o)  ((o) ^ (((o) >> 3) & 0x70))   // 128B-row swizzle (GEMM tiles)
#define ASW(o)  ((o) ^ (((o) >> 4) & 0x70))   // 256B-row swizzle (attn tiles)

__device__ __forceinline__ void ldsm4(uint32_t* r, uint32_t addr) {
    asm volatile("ldmatrix.sync.aligned.m8n8.x4.shared.b16 {%0,%1,%2,%3}, [%4];"
        : "=r"(r[0]), "=r"(r[1]), "=r"(r[2]), "=r"(r[3]) : "r"(addr));
}
__device__ __forceinline__ void ldsm4t(uint32_t* r, uint32_t addr) {
    asm volatile("ldmatrix.sync.aligned.m8n8.x4.trans.shared.b16 {%0,%1,%2,%3}, [%4];"
        : "=r"(r[0]), "=r"(r[1]), "=r"(r[2]), "=r"(r[3]) : "r"(addr));
}
__device__ __forceinline__ void mma_bf16(float* c, const uint32_t* a, const uint32_t* b) {
    asm volatile("mma.sync.aligned.m16n8k16.row.col.f32.bf16.bf16.f32 "
        "{%0,%1,%2,%3}, {%4,%5,%6,%7}, {%8,%9}, {%0,%1,%2,%3};"
        : "+f"(c[0]), "+f"(c[1]), "+f"(c[2]), "+f"(c[3])
        : "r"(a[0]), "r"(a[1]), "r"(a[2]), "r"(a[3]), "r"(b[0]), "r"(b[1]));
}
#define CP_ASYNC(dst, src, sz) \
    asm volatile("cp.async.cg.shared.global [%0], [%1], 16, %2;" \
        :: "r"(dst), "l"(src), "r"(sz) : "memory")
#define CP_COMMIT() asm volatile("cp.async.commit_group;" ::: "memory")
#define CP_WAIT(n)  asm volatile("cp.async.wait_group %0;" :: "n"(n) : "memory")

__device__ __forceinline__ uint32_t pack_bf2(__nv_bfloat16 lo, __nv_bfloat16 hi) {
    __nv_bfloat162 t; t.x = lo; t.y = hi;
    return *reinterpret_cast<uint32_t*>(&t);
}

// ======================================================================
// fp32 -> bf16 hi/lo splits
// ======================================================================
__global__ __launch_bounds__(256) void conv_split(
    const float* __restrict__ s, __nv_bfloat16* __restrict__ h,
    __nv_bfloat16* __restrict__ l, int n)
{
    int i = blockIdx.x * 256 + threadIdx.x;
    if (i < n) {
        float v = s[i];
        __nv_bfloat16 hi = __float2bfloat16(v);
        h[i] = hi;
        l[i] = __float2bfloat16(v - __bfloat162float(hi));
    }
}

__global__ __launch_bounds__(256) void conv_w3(
    const float* __restrict__ s1, __nv_bfloat16* __restrict__ h1, __nv_bfloat16* __restrict__ l1, int n1,
    const float* __restrict__ s2, __nv_bfloat16* __restrict__ h2, __nv_bfloat16* __restrict__ l2, int n2,
    const float* __restrict__ s3, __nv_bfloat16* __restrict__ h3, __nv_bfloat16* __restrict__ l3, int n3)
{
    int i = blockIdx.x * 256 + threadIdx.x;
    const float* s; __nv_bfloat16 *h, *l; int j;
    if (i < n1)           { s = s1; h = h1; l = l1; j = i; }
    else if (i < n1 + n2) { s = s2; h = h2; l = l2; j = i - n1; }
    else if (i < n1 + n2 + n3) { s = s3; h = h3; l = l3; j = i - n1 - n2; }
    else return;
    float v = s[j];
    __nv_bfloat16 hi = __float2bfloat16(v);
    h[j] = hi;
    l[j] = __float2bfloat16(v - __bfloat162float(hi));
}

// ======================================================================
// mma.sync bf16-split NT GEMM body (16 warps, as R6, passing)
// ======================================================================
#define TILE_B   16384
#define BUF_B    (4 * TILE_B)
#define GEMM_SMEM (2 * BUF_B + 1024)

__device__ __forceinline__ void gemm_body(
    const __nv_bfloat16* __restrict__ Ah, const __nv_bfloat16* __restrict__ Al,
    const __nv_bfloat16* __restrict__ Bh, const __nv_bfloat16* __restrict__ Bl,
    float* __restrict__ C, int N, int K, int bm, int bn, uint32_t smem)
{
    const int tid  = threadIdx.x;
    const int wid  = tid >> 5, lane = tid & 31;
    const int wm   = (wid >> 2) * 32;
    const int wn   = (wid & 3) * 32;
    const int nchunk = K >> 6;

    auto load_chunk = [&](int c, int buf) {
        const uint32_t base = smem + buf * BUF_B;
        const int k0 = c * 64;
#pragma unroll
        for (int u = tid; u < 1024; u += 512) {
            int row = u >> 3, seg = u & 7;
            uint32_t so = SWZ((uint32_t)(row * 128 + seg * 16));
            size_t ga = (size_t)(bm + row) * K + k0 + seg * 8;
            CP_ASYNC(base + so,              Ah + ga, 16);
            CP_ASYNC(base + TILE_B + so,     Al + ga, 16);
            int n = bn + row;
            int sz = (n < N) ? 16 : 0;
            size_t gb = (size_t)(n < N ? n : 0) * K + k0 + seg * 8;
            CP_ASYNC(base + 2 * TILE_B + so, Bh + gb, sz);
            CP_ASYNC(base + 3 * TILE_B + so, Bl + gb, sz);
        }
        CP_COMMIT();
    };

    float acc[2][4][4];
#pragma unroll
    for (int i = 0; i < 2; i++)
#pragma unroll
        for (int j = 0; j < 4; j++)
#pragma unroll
            for (int q = 0; q < 4; q++) acc[i][j][q] = 0.f;

    load_chunk(0, 0);

    for (int c = 0; c < nchunk; c++) {
        const int buf = c & 1;
        if (c + 1 < nchunk) {
            load_chunk(c + 1, buf ^ 1);
            CP_WAIT(1);
        } else {
            CP_WAIT(0);
        }
        __syncthreads();

        const uint32_t sa_h = smem + buf * BUF_B;
        const uint32_t sa_l = sa_h + TILE_B;
        const uint32_t sb_h = sa_h + 2 * TILE_B;
        const uint32_t sb_l = sa_h + 3 * TILE_B;

#pragma unroll
        for (int ks = 0; ks < 4; ks++) {
            const int kk = ks * 16;
            uint32_t ah[2][4], al[2][4], bh[2][4], bl[2][4];
            {
                int r = lane & 15, ck = lane >> 4;
#pragma unroll
                for (int mt = 0; mt < 2; mt++) {
                    uint32_t off = SWZ((uint32_t)((wm + mt * 16 + r) * 128 + (kk + ck * 8) * 2));
                    ldsm4(ah[mt], sa_h + off);
                    ldsm4(al[mt], sa_l + off);
                }
            }
            {
                int grp = lane >> 3, ln = lane & 7;
#pragma unroll
                for (int np = 0; np < 2; np++) {
                    int n = wn + np * 16 + (grp >> 1) * 8 + ln;
                    int kc = kk + (grp & 1) * 8;
                    uint32_t off = SWZ((uint32_t)(n * 128 + kc * 2));
                    ldsm4(bh[np], sb_h + off);
                    ldsm4(bl[np], sb_l + off);
                }
            }
#pragma unroll
            for (int mt = 0; mt < 2; mt++)
#pragma unroll
                for (int nt = 0; nt < 4; nt++) {
                    const uint32_t* ph = &bh[nt >> 1][(nt & 1) * 2];
                    const uint32_t* pl = &bl[nt >> 1][(nt & 1) * 2];
                    mma_bf16(acc[mt][nt], ah[mt], ph);
                    mma_bf16(acc[mt][nt], ah[mt], pl);
                    mma_bf16(acc[mt][nt], al[mt], ph);
                }
        }
        __syncthreads();
    }

#pragma unroll
    for (int mt = 0; mt < 2; mt++) {
        int r0 = bm + wm + mt * 16 + (lane >> 2);
#pragma unroll
        for (int nt = 0; nt < 4; nt++) {
            int col = bn + wn + nt * 8 + (lane & 3) * 2;
            if (col < N) {
                float* c0 = C + (size_t)r0 * N + col;
                float* c1 = C + (size_t)(r0 + 8) * N + col;
                c0[0] = acc[mt][nt][0]; c0[1] = acc[mt][nt][1];
                c1[0] = acc[mt][nt][2]; c1[1] = acc[mt][nt][3];
            }
        }
    }
}

__global__ __launch_bounds__(512) void gemm_mma512(
    const __nv_bfloat16* __restrict__ Ah, const __nv_bfloat16* __restrict__ Al,
    const __nv_bfloat16* __restrict__ Bh, const __nv_bfloat16* __restrict__ Bl,
    float* __restrict__ C, int N, int K)
{
    extern __shared__ char smraw[];
    const uint32_t smem0 = smem_u32(smraw);
    const uint32_t smem  = (smem0 + 1023) & ~1023u;
    gemm_body(Ah, Al, Bh, Bl, C, N, K, blockIdx.y * 128, blockIdx.x * 128, smem);
}

#define QTILES 7
__global__ __launch_bounds__(512) void gemm_qkv(
    const __nv_bfloat16* __restrict__ Ah, const __nv_bfloat16* __restrict__ Al)
{
    extern __shared__ char smraw[];
    const uint32_t smem0 = smem_u32(smraw);
    const uint32_t smem  = (smem0 + 1023) & ~1023u;
    const int bx = blockIdx.x;
    if (bx < QTILES)
        gemm_body(Ah, Al, g_wqh, g_wql, g_abq, NQ, DM,
                  blockIdx.y * 128, bx * 128, smem);
    else
        gemm_body(Ah, Al, g_wkh, g_wkl, g_abkv, NKV, DM,
                  blockIdx.y * 128, (bx - QTILES) * 128, smem);
}

// ======================================================================
// qkv: rank contraction + rotary (fp32 trig) -> bf16 hi/lo q,k,v [b,h,t,d]
// ======================================================================
__global__ __launch_bounds__(128) void qkv_kernel()
{
    const int m = blockIdx.x;
    const int b = m >> 11;
    const int t = m & (TT - 1);
    const int d = threadIdx.x;

    __shared__ float aq  [RQ][16];
    __shared__ float bq  [RQ][128];
    __shared__ float akv [RKV][16];
    __shared__ float braw[RKV][128];
    __shared__ float brot[RKV][128];

    const float* abq = g_abq + (size_t)m * NQ;
    for (int idx = d; idx < NQ; idx += 128) {
        int r = idx / CH, c = idx - r * CH;
        float v = abq[idx];
        if (c < 16) aq[r][c] = v; else bq[r][c - 16] = v;
    }
    const float* abkv = g_abkv + (size_t)m * NKV;
    for (int idx = d; idx < NKV; idx += 128) {
        int r = idx / CH, c = idx - r * CH;
        float v = abkv[idx];
        if (c < 16) akv[r][c] = v; else braw[r][c - 16] = v;
    }
    __syncthreads();

    {
        int j = d & 63;
        float inv = powf(1e-4f, (float)j * (1.f / 64.f));   // (1/10000)^(j/64)
        float sv, cv;
        sincosf((float)t * inv, &sv, &cv);
#pragma unroll
        for (int r = 0; r < RKV; r++) {
            float x1 = braw[r][j], x2 = braw[r][j + 64];
            brot[r][d] = (d < 64) ? (x1 * cv + x2 * sv) : (-x1 * sv + x2 * cv);
        }
    }

    const size_t base = (((size_t)b * NH) * TT + t) * DH + d;
#pragma unroll
    for (int h = 0; h < NH; h++) {
        float qv = 0.f;
#pragma unroll
        for (int r = 0; r < RQ; r++) qv += aq[r][h] * bq[r][d];
        qv *= (1.f / 6.f);
        float kv = (akv[0][h] * brot[0][d] + akv[1][h] * brot[1][d]) * 0.5f;
        float vv = (akv[2][h] * brot[2][d] + akv[3][h] * brot[3][d]) * 0.5f;
        size_t o = base + (size_t)h * TT * DH;
        __nv_bfloat16 qhh = __float2bfloat16(qv);
        __nv_bfloat16 khh = __float2bfloat16(kv);
        __nv_bfloat16 vhh = __float2bfloat16(vv);
        g_qh[o] = qhh; g_ql[o] = __float2bfloat16(qv - __bfloat162float(qhh));
        g_kh[o] = khh; g_kl[o] = __float2bfloat16(kv - __bfloat162float(khh));
        g_vh[o] = vhh; g_vl[o] = __float2bfloat16(vv - __bfloat162float(vhh));
    }
}

// ======================================================================
// flash attention, causal, mma.sync bf16 split, 16 warps / 256-row Q tile.
// grid (T/256, NH, NB), 512 threads. Single K stage + single V stage with
// split commit groups: K(kt+1) loads overlap PV(kt); V(kt+1) overlap S(kt+1).
// ======================================================================
#define ATTN_SMEM (196608 + 1024)

__global__ __launch_bounds__(512) void attn_mma()
{
    extern __shared__ char smraw[];
    const uint32_t sb0 = smem_u32(smraw);
    const uint32_t sb = (sb0 + 1023) & ~1023u;

    const int tid = threadIdx.x, wid = tid >> 5, lane = tid & 31;
    const int qt = (int)gridDim.x - 1 - (int)blockIdx.x;   // heavy tiles first
    const int h = blockIdx.y, b = blockIdx.z;
    const size_t bh = ((size_t)b * NH + h) * TT;
    const int nkt = 4 * qt + 4;
    const int wbase = qt * 256 + wid * 16;

    const uint32_t sQh = sb, sQl = sb + 65536;
    const uint32_t sKh = sb + 131072, sKl = sKh + 16384;
    const uint32_t sVh = sb + 163840, sVl = sVh + 16384;

    // Q loads (256 rows hi/lo) — bundled into the K(0) commit group
    {
        const char* qh = (const char*)g_qh + (bh + (size_t)qt * 256) * 256;
        const char* ql = (const char*)g_ql + (bh + (size_t)qt * 256) * 256;
#pragma unroll
        for (int u = tid; u < 4096; u += 512) {
            int row = u >> 4, seg = u & 15;
            uint32_t off = ASW((uint32_t)(row * 256 + seg * 16));
            int go = row * 256 + seg * 16;
            CP_ASYNC(sQh + off, qh + go, 16);
            CP_ASYNC(sQl + off, ql + go, 16);
        }
    }
    auto load_k = [&](int kt) {
        const char* kh = (const char*)g_kh + (bh + (size_t)kt * 64) * 256;
        const char* kl = (const char*)g_kl + (bh + (size_t)kt * 64) * 256;
#pragma unroll
        for (int u = tid; u < 1024; u += 512) {
            int row = u >> 4, seg = u & 15;
            uint32_t off = ASW((uint32_t)(row * 256 + seg * 16));
            int go = row * 256 + seg * 16;
            CP_ASYNC(sKh + off, kh + go, 16);
            CP_ASYNC(sKl + off, kl + go, 16);
        }
        CP_COMMIT();
    };
    auto load_v = [&](int kt) {
        const char* vh = (const char*)g_vh + (bh + (size_t)kt * 64) * 256;
        const char* vl = (const char*)g_vl + (bh + (size_t)kt * 64) * 256;
#pragma unroll
        for (int u = tid; u < 1024; u += 512) {
            int row = u >> 4, seg = u & 15;
            uint32_t off = ASW((uint32_t)(row * 256 + seg * 16));
            int go = row * 256 + seg * 16;
            CP_ASYNC(sVh + off, vh + go, 16);
            CP_ASYNC(sVl + off, vl + go, 16);
        }
        CP_COMMIT();
    };
    load_k(0);   // commit group = {Q, K0}
    load_v(0);   // group {V0}

    float oacc[16][4];
#pragma unroll
    for (int dt = 0; dt < 16; dt++)
#pragma unroll
        for (int e = 0; e < 4; e++) oacc[dt][e] = 0.f;
    float rM0 = -1e30f, rM1 = -1e30f, rL0 = 0.f, rL1 = 0.f;

    const float scale = 0.08838834764831845f;
    const int r0g = wbase + (lane >> 2);

    for (int kt = 0; kt < nkt; kt++) {
        CP_WAIT(1);            // K(kt) (and Q) arrived; V(kt) may be in flight
        __syncthreads();

        const bool skip = (kt * 64 > wbase + 15);
        float sacc[8][4];
        if (!skip) {
#pragma unroll
            for (int nt = 0; nt < 8; nt++)
#pragma unroll
                for (int e = 0; e < 4; e++) sacc[nt][e] = 0.f;
#pragma unroll
            for (int ks = 0; ks < 8; ks++) {
                uint32_t ah[4], al[4];
                {
                    int r = lane & 15, ck = lane >> 4;
                    uint32_t off = ASW((uint32_t)((wid * 16 + r) * 256 + (ks * 16 + ck * 8) * 2));
                    ldsm4(ah, sQh + off);
                    ldsm4(al, sQl + off);
                }
#pragma unroll
                for (int ng = 0; ng < 4; ng++) {
                    uint32_t bh4[4], bl4[4];
                    {
                        int grp = lane >> 3, ln = lane & 7;
                        int n = ng * 16 + (grp >> 1) * 8 + ln;
                        int kc = ks * 16 + (grp & 1) * 8;
                        uint32_t off = ASW((uint32_t)(n * 256 + kc * 2));
                        ldsm4(bh4, sKh + off);
                        ldsm4(bl4, sKl + off);
                    }
                    mma_bf16(sacc[ng * 2], ah, bh4);
                    mma_bf16(sacc[ng * 2], ah, bl4);
                    mma_bf16(sacc[ng * 2], al, bh4);
                    mma_bf16(sacc[ng * 2 + 1], ah, bh4 + 2);
                    mma_bf16(sacc[ng * 2 + 1], ah, bl4 + 2);
                    mma_bf16(sacc[ng * 2 + 1], al, bh4 + 2);
                }
            }
        }
        __syncthreads();                 // K buffer consumed by all warps
        if (kt + 1 < nkt) load_k(kt + 1);   // overlaps softmax+PV below
        if (kt + 1 < nkt) { CP_WAIT(1); } else { CP_WAIT(0); }   // V(kt) ready
        __syncthreads();

        if (!skip) {
            const bool domask = (kt * 64 + 63 > wbase);
            float mx0 = -1e30f, mx1 = -1e30f;
#pragma unroll
            for (int nt = 0; nt < 8; nt++) {
                int c0 = kt * 64 + nt * 8 + (lane & 3) * 2;
#pragma unroll
                for (int e = 0; e < 4; e++) {
                    float v = sacc[nt][e] * scale;
                    if (domask) {
                        int cc = c0 + (e & 1);
                        int rr = r0g + ((e >> 1) << 3);
                        if (cc > rr) v = -1e30f;
                    }
                    sacc[nt][e] = v;
                }
                mx0 = fmaxf(mx0, fmaxf(sacc[nt][0], sacc[nt][1]));
                mx1 = fmaxf(mx1, fmaxf(sacc[nt][2], sacc[nt][3]));
            }
            mx0 = fmaxf(mx0, __shfl_xor_sync(0xffffffffu, mx0, 1));
            mx0 = fmaxf(mx0, __shfl_xor_sync(0xffffffffu, mx0, 2));
            mx1 = fmaxf(mx1, __shfl_xor_sync(0xffffffffu, mx1, 1));
            mx1 = fmaxf(mx1, __shfl_xor_sync(0xffffffffu, mx1, 2));

            float nM0 = fmaxf(rM0, mx0), nM1 = fmaxf(rM1, mx1);
            float cor0 = __expf(rM0 - nM0), cor1 = __expf(rM1 - nM1);
            rM0 = nM0; rM1 = nM1;

            float sum0 = 0.f, sum1 = 0.f;
            uint32_t pH01[8], pH23[8], pL01[8], pL23[8];
#pragma unroll
            for (int nt = 0; nt < 8; nt++) {
                float p0 = __expf(sacc[nt][0] - nM0);
                float p1 = __expf(sacc[nt][1] - nM0);
                float p2 = __expf(sacc[nt][2] - nM1);
                float p3 = __expf(sacc[nt][3] - nM1);
                sum0 += p0 + p1; sum1 += p2 + p3;
                __nv_bfloat16 h0 = __float2bfloat16(p0), h1 = __float2bfloat16(p1);
                __nv_bfloat16 h2 = __float2bfloat16(p2), h3 = __float2bfloat16(p3);
                pH01[nt] = pack_bf2(h0, h1);
                pH23[nt] = pack_bf2(h2, h3);
                pL01[nt] = pack_bf2(__float2bfloat16(p0 - __bfloat162float(h0)),
                                    __float2bfloat16(p1 - __bfloat162float(h1)));
                pL23[nt] = pack_bf2(__float2bfloat16(p2 - __bfloat162float(h2)),
                                    __float2bfloat16(p3 - __bfloat162float(h3)));
            }
            sum0 += __shfl_xor_sync(0xffffffffu, sum0, 1);
            sum0 += __shfl_xor_sync(0xffffffffu, sum0, 2);
            sum1 += __shfl_xor_sync(0xffffffffu, sum1, 1);
            sum1 += __shfl_xor_sync(0xffffffffu, sum1, 2);
            rL0 = rL0 * cor0 + sum0;
            rL1 = rL1 * cor1 + sum1;

#pragma unroll
            for (int dt = 0; dt < 16; dt++) {
                oacc[dt][0] *= cor0; oacc[dt][1] *= cor0;
                oacc[dt][2] *= cor1; oacc[dt][3] *= cor1;
            }

#pragma unroll
            for (int k2 = 0; k2 < 4; k2++) {
                uint32_t aH[4] = {pH01[2 * k2], pH23[2 * k2], pH01[2 * k2 + 1], pH23[2 * k2 + 1]};
                uint32_t aL[4] = {pL01[2 * k2], pL23[2 * k2], pL01[2 * k2 + 1], pL23[2 * k2 + 1]};
                int krow = k2 * 16 + ((lane >> 3) & 1) * 8 + (lane & 7);
#pragma unroll
                for (int dg = 0; dg < 8; dg++) {
                    int dcol = dg * 16 + (lane >> 4) * 8;
                    uint32_t off = ASW((uint32_t)(krow * 256 + dcol * 2));
                    uint32_t vh4[4], vl4[4];
                    ldsm4t(vh4, sVh + off);
                    ldsm4t(vl4, sVl + off);
                    mma_bf16(oacc[dg * 2], aH, vh4);
                    mma_bf16(oacc[dg * 2], aH, vl4);
                    mma_bf16(oacc[dg * 2], aL, vh4);
                    mma_bf16(oacc[dg * 2 + 1], aH, vh4 + 2);
                    mma_bf16(oacc[dg * 2 + 1], aH, vl4 + 2);
                    mma_bf16(oacc[dg * 2 + 1], aL, vh4 + 2);
                }
            }
        }
        __syncthreads();                 // V buffer consumed by all warps
        if (kt + 1 < nkt) load_v(kt + 1);   // overlaps next S
    }

    // ---- normalize + split + store bf16 hi/lo y ----
    float il0 = 1.f / rL0, il1 = 1.f / rL1;
    size_t row0 = ((size_t)b * TT + r0g) * DM + h * DH;
    size_t row1 = row0 + (size_t)8 * DM;
#pragma unroll
    for (int dt = 0; dt < 16; dt++) {
        int c = dt * 8 + (lane & 3) * 2;
        float v0 = oacc[dt][0] * il0, v1 = oacc[dt][1] * il0;
        float v2 = oacc[dt][2] * il1, v3 = oacc[dt][3] * il1;
        __nv_bfloat16 h0 = __float2bfloat16(v0), h1 = __float2bfloat16(v1);
        __nv_bfloat16 h2 = __float2bfloat16(v2), h3 = __float2bfloat16(v3);
        *(uint32_t*)(g_yh + row0 + c) = pack_bf2(h0, h1);
        *(uint32_t*)(g_yh + row1 + c) = pack_bf2(h2, h3);
        *(uint32_t*)(g_yl + row0 + c) = pack_bf2(__float2bfloat16(v0 - __bfloat162float(h0)),
                                                 __float2bfloat16(v1 - __bfloat162float(h1)));
        *(uint32_t*)(g_yl + row1 + c) = pack_bf2(__float2bfloat16(v2 - __bfloat162float(h2)),
                                                 __float2bfloat16(v3 - __bfloat162float(h3)));
    }
}

// ======================================================================
extern "C" void kernel_launch(void* const* d_in, const int* in_sizes, int n_in,
                              void* d_out, int out_size)
{
    const float* x   = (const float*)d_in[0];
    const float* Wq  = (const float*)d_in[1];
    const float* Wkv = (const float*)d_in[2];
    const float* Wo  = (const float*)d_in[3];
    float* out = (float*)d_out;

    __nv_bfloat16 *xh, *xl, *wqh, *wql, *wkh, *wkl, *woh, *wol, *yh, *yl;
    cudaGetSymbolAddress((void**)&xh,  g_xh);  cudaGetSymbolAddress((void**)&xl,  g_xl);
    cudaGetSymbolAddress((void**)&wqh, g_wqh); cudaGetSymbolAddress((void**)&wql, g_wql);
    cudaGetSymbolAddress((void**)&wkh, g_wkh); cudaGetSymbolAddress((void**)&wkl, g_wkl);
    cudaGetSymbolAddress((void**)&woh, g_woh); cudaGetSymbolAddress((void**)&wol, g_wol);
    cudaGetSymbolAddress((void**)&yh,  g_yh);  cudaGetSymbolAddress((void**)&yl,  g_yl);

    cudaFuncSetAttribute(gemm_mma512, cudaFuncAttributeMaxDynamicSharedMemorySize, GEMM_SMEM);
    cudaFuncSetAttribute(gemm_qkv,    cudaFuncAttributeMaxDynamicSharedMemorySize, GEMM_SMEM);
    cudaFuncSetAttribute(attn_mma,    cudaFuncAttributeMaxDynamicSharedMemorySize, ATTN_SMEM);

    // 0) fp32 -> bf16 hi/lo splits (x, then all weights fused)
    conv_split<<<(BT * DM + 255) / 256, 256>>>(x, xh, xl, BT * DM);
    {
        int n1 = NQ * DM, n2 = NKV * DM, n3 = DM * DM;
        conv_w3<<<(n1 + n2 + n3 + 255) / 256, 256>>>(
            Wq, wqh, wql, n1, Wkv, wkh, wkl, n2, Wo, woh, wol, n3);
    }
    // 1) fused ab_q / ab_kv projections (one launch, 384 CTAs)
    {
        dim3 g(QTILES + 5, BT / 128);
        gemm_qkv<<<g, 512, GEMM_SMEM>>>(xh, xl);
    }
    // 2) q,k,v (+rotary) -> bf16 hi/lo
    qkv_kernel<<<BT, 128>>>();
    // 3) causal attention (tensor cores, 16 warps) -> yh/yl directly
    {
        dim3 g(TT / 256, NH, NB);
        attn_mma<<<g, 512, ATTN_SMEM>>>();
    }
    // 4) out = y @ W_o^T (4096 x 2048)
    {
        dim3 g(DM / 128, BT / 128);
        gemm_mma512<<<g, 512, GEMM_SMEM>>>(yh, yl, woh, wol, out, DM, DM);
    }
}

// round 8
// speedup vs baseline: 1.2778x; 1.2778x over previous
#include <cuda_runtime.h>
#include <cuda_bf16.h>
#include <cstdint>
#include <math.h>

// ---------------- problem constants ----------------
#define NB     2
#define TT     2048
#define BT     4096      // NB*TT tokens
#define DM     2048
#define NH     16
#define DH     128
#define CH     144       // NH + DH
#define RQ     6
#define RKV    4
#define NQ     864       // RQ*CH
#define NKV    576       // RKV*CH

// ---------------- scratch (device globals; no allocs allowed) ----------------
__device__ float g_abq [BT * NQ];
__device__ float g_abkv[BT * NKV];

// bf16 hi/lo split scratch
__device__ __nv_bfloat16 g_xh [BT * DM],  g_xl [BT * DM];
__device__ __nv_bfloat16 g_wqh[NQ * DM],  g_wql[NQ * DM];
__device__ __nv_bfloat16 g_wkh[NKV * DM], g_wkl[NKV * DM];
__device__ __nv_bfloat16 g_woh[DM * DM],  g_wol[DM * DM];
__device__ __nv_bfloat16 g_yh [BT * DM],  g_yl [BT * DM];

// q/k/v bf16 hi/lo, layout [b,h,t,d]
#define QKV_ELEMS (NB * NH * TT * DH)
__device__ __nv_bfloat16 g_qh[QKV_ELEMS], g_ql[QKV_ELEMS];
__device__ __nv_bfloat16 g_kh[QKV_ELEMS], g_kl[QKV_ELEMS];
__device__ __nv_bfloat16 g_vh[QKV_ELEMS], g_vl[QKV_ELEMS];

// ================= helpers =================
__device__ __forceinline__ uint32_t smem_u32(const void* p) {
    uint32_t a;
    asm("{ .reg .u64 t; cvta.to.shared.u64 t, %1; cvt.u32.u64 %0, t; }" : "=r"(a) : "l"(p));
    return a;
}
#define SWZ(o)  ((o) ^ (((o) >> 3) & 0x70))   // 128B-row swizzle (GEMM tiles)
#define ASW(o)  ((o) ^ (((o) >> 4) & 0x70))   // 256B-row swizzle (attn tiles)

__device__ __forceinline__ void ldsm4(uint32_t* r, uint32_t addr) {
    asm volatile("ldmatrix.sync.aligned.m8n8.x4.shared.b16 {%0,%1,%2,%3}, [%4];"
        : "=r"(r[0]), "=r"(r[1]), "=r"(r[2]), "=r"(r[3]) : "r"(addr));
}
__device__ __forceinline__ void ldsm4t(uint32_t* r, uint32_t addr) {
    asm volatile("ldmatrix.sync.aligned.m8n8.x4.trans.shared.b16 {%0,%1,%2,%3}, [%4];"
        : "=r"(r[0]), "=r"(r[1]), "=r"(r[2]), "=r"(r[3]) : "r"(addr));
}
__device__ __forceinline__ void mma_bf16(float* c, const uint32_t* a, const uint32_t* b) {
    asm volatile("mma.sync.aligned.m16n8k16.row.col.f32.bf16.bf16.f32 "
        "{%0,%1,%2,%3}, {%4,%5,%6,%7}, {%8,%9}, {%0,%1,%2,%3};"
        : "+f"(c[0]), "+f"(c[1]), "+f"(c[2]), "+f"(c[3])
        : "r"(a[0]), "r"(a[1]), "r"(a[2]), "r"(a[3]), "r"(b[0]), "r"(b[1]));
}
#define CP_ASYNC(dst, src, sz) \
    asm volatile("cp.async.cg.shared.global [%0], [%1], 16, %2;" \
        :: "r"(dst), "l"(src), "r"(sz) : "memory")
#define CP_COMMIT() asm volatile("cp.async.commit_group;" ::: "memory")
#define CP_WAIT(n)  asm volatile("cp.async.wait_group %0;" :: "n"(n) : "memory")

__device__ __forceinline__ uint32_t pack_bf2(__nv_bfloat16 lo, __nv_bfloat16 hi) {
    __nv_bfloat162 t; t.x = lo; t.y = hi;
    return *reinterpret_cast<uint32_t*>(&t);
}

// ======================================================================
// fp32 -> bf16 hi/lo splits
// ======================================================================
__global__ __launch_bounds__(256) void conv_split(
    const float* __restrict__ s, __nv_bfloat16* __restrict__ h,
    __nv_bfloat16* __restrict__ l, int n)
{
    int i = blockIdx.x * 256 + threadIdx.x;
    if (i < n) {
        float v = s[i];
        __nv_bfloat16 hi = __float2bfloat16(v);
        h[i] = hi;
        l[i] = __float2bfloat16(v - __bfloat162float(hi));
    }
}

__global__ __launch_bounds__(256) void conv_w3(
    const float* __restrict__ s1, __nv_bfloat16* __restrict__ h1, __nv_bfloat16* __restrict__ l1, int n1,
    const float* __restrict__ s2, __nv_bfloat16* __restrict__ h2, __nv_bfloat16* __restrict__ l2, int n2,
    const float* __restrict__ s3, __nv_bfloat16* __restrict__ h3, __nv_bfloat16* __restrict__ l3, int n3)
{
    int i = blockIdx.x * 256 + threadIdx.x;
    const float* s; __nv_bfloat16 *h, *l; int j;
    if (i < n1)           { s = s1; h = h1; l = l1; j = i; }
    else if (i < n1 + n2) { s = s2; h = h2; l = l2; j = i - n1; }
    else if (i < n1 + n2 + n3) { s = s3; h = h3; l = l3; j = i - n1 - n2; }
    else return;
    float v = s[j];
    __nv_bfloat16 hi = __float2bfloat16(v);
    h[j] = hi;
    l[j] = __float2bfloat16(v - __bfloat162float(hi));
}

// ======================================================================
// mma.sync bf16-split NT GEMM body (16 warps, as R6, passing)
// ======================================================================
#define TILE_B   16384
#define BUF_B    (4 * TILE_B)
#define GEMM_SMEM (2 * BUF_B + 1024)

__device__ __forceinline__ void gemm_body(
    const __nv_bfloat16* __restrict__ Ah, const __nv_bfloat16* __restrict__ Al,
    const __nv_bfloat16* __restrict__ Bh, const __nv_bfloat16* __restrict__ Bl,
    float* __restrict__ C, int N, int K, int bm, int bn, uint32_t smem)
{
    const int tid  = threadIdx.x;
    const int wid  = tid >> 5, lane = tid & 31;
    const int wm   = (wid >> 2) * 32;
    const int wn   = (wid & 3) * 32;
    const int nchunk = K >> 6;

    auto load_chunk = [&](int c, int buf) {
        const uint32_t base = smem + buf * BUF_B;
        const int k0 = c * 64;
#pragma unroll
        for (int u = tid; u < 1024; u += 512) {
            int row = u >> 3, seg = u & 7;
            uint32_t so = SWZ((uint32_t)(row * 128 + seg * 16));
            size_t ga = (size_t)(bm + row) * K + k0 + seg * 8;
            CP_ASYNC(base + so,              Ah + ga, 16);
            CP_ASYNC(base + TILE_B + so,     Al + ga, 16);
            int n = bn + row;
            int sz = (n < N) ? 16 : 0;
            size_t gb = (size_t)(n < N ? n : 0) * K + k0 + seg * 8;
            CP_ASYNC(base + 2 * TILE_B + so, Bh + gb, sz);
            CP_ASYNC(base + 3 * TILE_B + so, Bl + gb, sz);
        }
        CP_COMMIT();
    };

    float acc[2][4][4];
#pragma unroll
    for (int i = 0; i < 2; i++)
#pragma unroll
        for (int j = 0; j < 4; j++)
#pragma unroll
            for (int q = 0; q < 4; q++) acc[i][j][q] = 0.f;

    load_chunk(0, 0);

    for (int c = 0; c < nchunk; c++) {
        const int buf = c & 1;
        if (c + 1 < nchunk) {
            load_chunk(c + 1, buf ^ 1);
            CP_WAIT(1);
        } else {
            CP_WAIT(0);
        }
        __syncthreads();

        const uint32_t sa_h = smem + buf * BUF_B;
        const uint32_t sa_l = sa_h + TILE_B;
        const uint32_t sb_h = sa_h + 2 * TILE_B;
        const uint32_t sb_l = sa_h + 3 * TILE_B;

#pragma unroll
        for (int ks = 0; ks < 4; ks++) {
            const int kk = ks * 16;
            uint32_t ah[2][4], al[2][4], bh[2][4], bl[2][4];
            {
                int r = lane & 15, ck = lane >> 4;
#pragma unroll
                for (int mt = 0; mt < 2; mt++) {
                    uint32_t off = SWZ((uint32_t)((wm + mt * 16 + r) * 128 + (kk + ck * 8) * 2));
                    ldsm4(ah[mt], sa_h + off);
                    ldsm4(al[mt], sa_l + off);
                }
            }
            {
                int grp = lane >> 3, ln = lane & 7;
#pragma unroll
                for (int np = 0; np < 2; np++) {
                    int n = wn + np * 16 + (grp >> 1) * 8 + ln;
                    int kc = kk + (grp & 1) * 8;
                    uint32_t off = SWZ((uint32_t)(n * 128 + kc * 2));
                    ldsm4(bh[np], sb_h + off);
                    ldsm4(bl[np], sb_l + off);
                }
            }
#pragma unroll
            for (int mt = 0; mt < 2; mt++)
#pragma unroll
                for (int nt = 0; nt < 4; nt++) {
                    const uint32_t* ph = &bh[nt >> 1][(nt & 1) * 2];
                    const uint32_t* pl = &bl[nt >> 1][(nt & 1) * 2];
                    mma_bf16(acc[mt][nt], ah[mt], ph);
                    mma_bf16(acc[mt][nt], ah[mt], pl);
                    mma_bf16(acc[mt][nt], al[mt], ph);
                }
        }
        __syncthreads();
    }

#pragma unroll
    for (int mt = 0; mt < 2; mt++) {
        int r0 = bm + wm + mt * 16 + (lane >> 2);
#pragma unroll
        for (int nt = 0; nt < 4; nt++) {
            int col = bn + wn + nt * 8 + (lane & 3) * 2;
            if (col < N) {
                float* c0 = C + (size_t)r0 * N + col;
                float* c1 = C + (size_t)(r0 + 8) * N + col;
                c0[0] = acc[mt][nt][0]; c0[1] = acc[mt][nt][1];
                c1[0] = acc[mt][nt][2]; c1[1] = acc[mt][nt][3];
            }
        }
    }
}

__global__ __launch_bounds__(512) void gemm_mma512(
    const __nv_bfloat16* __restrict__ Ah, const __nv_bfloat16* __restrict__ Al,
    const __nv_bfloat16* __restrict__ Bh, const __nv_bfloat16* __restrict__ Bl,
    float* __restrict__ C, int N, int K)
{
    extern __shared__ char smraw[];
    const uint32_t smem0 = smem_u32(smraw);
    const uint32_t smem  = (smem0 + 1023) & ~1023u;
    gemm_body(Ah, Al, Bh, Bl, C, N, K, blockIdx.y * 128, blockIdx.x * 128, smem);
}

#define QTILES 7
__global__ __launch_bounds__(512) void gemm_qkv(
    const __nv_bfloat16* __restrict__ Ah, const __nv_bfloat16* __restrict__ Al)
{
    extern __shared__ char smraw[];
    const uint32_t smem0 = smem_u32(smraw);
    const uint32_t smem  = (smem0 + 1023) & ~1023u;
    const int bx = blockIdx.x;
    if (bx < QTILES)
        gemm_body(Ah, Al, g_wqh, g_wql, g_abq, NQ, DM,
                  blockIdx.y * 128, bx * 128, smem);
    else
        gemm_body(Ah, Al, g_wkh, g_wkl, g_abkv, NKV, DM,
                  blockIdx.y * 128, (bx - QTILES) * 128, smem);
}

// ======================================================================
// qkv: rank contraction + rotary (fp32 trig) -> bf16 hi/lo q,k,v [b,h,t,d]
// ======================================================================
__global__ __launch_bounds__(128) void qkv_kernel()
{
    const int m = blockIdx.x;
    const int b = m >> 11;
    const int t = m & (TT - 1);
    const int d = threadIdx.x;

    __shared__ float aq  [RQ][16];
    __shared__ float bq  [RQ][128];
    __shared__ float akv [RKV][16];
    __shared__ float braw[RKV][128];
    __shared__ float brot[RKV][128];

    const float* abq = g_abq + (size_t)m * NQ;
    for (int idx = d; idx < NQ; idx += 128) {
        int r = idx / CH, c = idx - r * CH;
        float v = abq[idx];
        if (c < 16) aq[r][c] = v; else bq[r][c - 16] = v;
    }
    const float* abkv = g_abkv + (size_t)m * NKV;
    for (int idx = d; idx < NKV; idx += 128) {
        int r = idx / CH, c = idx - r * CH;
        float v = abkv[idx];
        if (c < 16) akv[r][c] = v; else braw[r][c - 16] = v;
    }
    __syncthreads();

    {
        int j = d & 63;
        float inv = powf(1e-4f, (float)j * (1.f / 64.f));   // (1/10000)^(j/64)
        float sv, cv;
        sincosf((float)t * inv, &sv, &cv);
#pragma unroll
        for (int r = 0; r < RKV; r++) {
            float x1 = braw[r][j], x2 = braw[r][j + 64];
            brot[r][d] = (d < 64) ? (x1 * cv + x2 * sv) : (-x1 * sv + x2 * cv);
        }
    }

    const size_t base = (((size_t)b * NH) * TT + t) * DH + d;
#pragma unroll
    for (int h = 0; h < NH; h++) {
        float qv = 0.f;
#pragma unroll
        for (int r = 0; r < RQ; r++) qv += aq[r][h] * bq[r][d];
        qv *= (1.f / 6.f);
        float kv = (akv[0][h] * brot[0][d] + akv[1][h] * brot[1][d]) * 0.5f;
        float vv = (akv[2][h] * brot[2][d] + akv[3][h] * brot[3][d]) * 0.5f;
        size_t o = base + (size_t)h * TT * DH;
        __nv_bfloat16 qhh = __float2bfloat16(qv);
        __nv_bfloat16 khh = __float2bfloat16(kv);
        __nv_bfloat16 vhh = __float2bfloat16(vv);
        g_qh[o] = qhh; g_ql[o] = __float2bfloat16(qv - __bfloat162float(qhh));
        g_kh[o] = khh; g_kl[o] = __float2bfloat16(kv - __bfloat162float(khh));
        g_vh[o] = vhh; g_vl[o] = __float2bfloat16(vv - __bfloat162float(vhh));
    }
}

// ======================================================================
// flash attention, causal, mma.sync bf16 split (R6 config — 930us proven).
// grid (T/128, NH, NB), 256 threads (8 warps x 16 q-rows), 2-stage K/V.
// ======================================================================
#define ATTN_SMEM (196608 + 1024)

__global__ __launch_bounds__(256) void attn_mma()
{
    extern __shared__ char smraw[];
    const uint32_t sb0 = smem_u32(smraw);
    const uint32_t sb = (sb0 + 1023) & ~1023u;

    const int tid = threadIdx.x, wid = tid >> 5, lane = tid & 31;
    const int qt = (int)gridDim.x - 1 - (int)blockIdx.x;   // heavy tiles first
    const int h = blockIdx.y, b = blockIdx.z;
    const size_t bh = ((size_t)b * NH + h) * TT;
    const int nkt = 2 * qt + 2;

    const uint32_t sQh = sb, sQl = sb + 32768;

    {
        const char* qh = (const char*)g_qh + (bh + (size_t)qt * 128) * 256;
        const char* ql = (const char*)g_ql + (bh + (size_t)qt * 128) * 256;
        for (int u = tid; u < 2048; u += 256) {
            int row = u >> 4, seg = u & 15;
            uint32_t off = ASW((uint32_t)(row * 256 + seg * 16));
            int go = row * 256 + seg * 16;
            CP_ASYNC(sQh + off, qh + go, 16);
            CP_ASYNC(sQl + off, ql + go, 16);
        }
    }
    auto load_kv = [&](int kt, int s) {
        uint32_t base = sb + 65536 + (uint32_t)s * 65536;
        const char* kh = (const char*)g_kh + (bh + (size_t)kt * 64) * 256;
        const char* kl = (const char*)g_kl + (bh + (size_t)kt * 64) * 256;
        const char* vh = (const char*)g_vh + (bh + (size_t)kt * 64) * 256;
        const char* vl = (const char*)g_vl + (bh + (size_t)kt * 64) * 256;
        for (int u = tid; u < 1024; u += 256) {
            int row = u >> 4, seg = u & 15;
            uint32_t off = ASW((uint32_t)(row * 256 + seg * 16));
            int go = row * 256 + seg * 16;
            CP_ASYNC(base + off,         kh + go, 16);
            CP_ASYNC(base + 16384 + off, kl + go, 16);
            CP_ASYNC(base + 32768 + off, vh + go, 16);
            CP_ASYNC(base + 49152 + off, vl + go, 16);
        }
        CP_COMMIT();
    };
    load_kv(0, 0);
    if (nkt > 1) load_kv(1, 1);

    float oacc[16][4];
#pragma unroll
    for (int dt = 0; dt < 16; dt++)
#pragma unroll
        for (int e = 0; e < 4; e++) oacc[dt][e] = 0.f;
    float rM0 = -1e30f, rM1 = -1e30f, rL0 = 0.f, rL1 = 0.f;

    const float scale = 0.08838834764831845f;
    const int r0g = qt * 128 + wid * 16 + (lane >> 2);

    for (int kt = 0; kt < nkt; kt++) {
        const int s = kt & 1;
        if (kt + 1 < nkt) { CP_WAIT(1); } else { CP_WAIT(0); }
        __syncthreads();
        const uint32_t base = sb + 65536 + (uint32_t)s * 65536;
        const uint32_t sKh = base, sKl = base + 16384;
        const uint32_t sVh = base + 32768, sVl = base + 49152;

        float sacc[8][4];
#pragma unroll
        for (int nt = 0; nt < 8; nt++)
#pragma unroll
            for (int e = 0; e < 4; e++) sacc[nt][e] = 0.f;

#pragma unroll
        for (int ks = 0; ks < 8; ks++) {
            uint32_t ah[4], al[4];
            {
                int r = lane & 15, ck = lane >> 4;
                uint32_t off = ASW((uint32_t)((wid * 16 + r) * 256 + (ks * 16 + ck * 8) * 2));
                ldsm4(ah, sQh + off);
                ldsm4(al, sQl + off);
            }
#pragma unroll
            for (int ng = 0; ng < 4; ng++) {
                uint32_t bh4[4], bl4[4];
                {
                    int grp = lane >> 3, ln = lane & 7;
                    int n = ng * 16 + (grp >> 1) * 8 + ln;
                    int kc = ks * 16 + (grp & 1) * 8;
                    uint32_t off = ASW((uint32_t)(n * 256 + kc * 2));
                    ldsm4(bh4, sKh + off);
                    ldsm4(bl4, sKl + off);
                }
                mma_bf16(sacc[ng * 2], ah, bh4);
                mma_bf16(sacc[ng * 2], ah, bl4);
                mma_bf16(sacc[ng * 2], al, bh4);
                mma_bf16(sacc[ng * 2 + 1], ah, bh4 + 2);
                mma_bf16(sacc[ng * 2 + 1], ah, bl4 + 2);
                mma_bf16(sacc[ng * 2 + 1], al, bh4 + 2);
            }
        }

        const bool domask = (kt >= 2 * qt);
        float mx0 = -1e30f, mx1 = -1e30f;
#pragma unroll
        for (int nt = 0; nt < 8; nt++) {
            int c0 = kt * 64 + nt * 8 + (lane & 3) * 2;
#pragma unroll
            for (int e = 0; e < 4; e++) {
                float v = sacc[nt][e] * scale;
                if (domask) {
                    int cc = c0 + (e & 1);
                    int rr = r0g + ((e >> 1) << 3);
                    if (cc > rr) v = -1e30f;
                }
                sacc[nt][e] = v;
            }
            mx0 = fmaxf(mx0, fmaxf(sacc[nt][0], sacc[nt][1]));
            mx1 = fmaxf(mx1, fmaxf(sacc[nt][2], sacc[nt][3]));
        }
        mx0 = fmaxf(mx0, __shfl_xor_sync(0xffffffffu, mx0, 1));
        mx0 = fmaxf(mx0, __shfl_xor_sync(0xffffffffu, mx0, 2));
        mx1 = fmaxf(mx1, __shfl_xor_sync(0xffffffffu, mx1, 1));
        mx1 = fmaxf(mx1, __shfl_xor_sync(0xffffffffu, mx1, 2));

        float nM0 = fmaxf(rM0, mx0), nM1 = fmaxf(rM1, mx1);
        float cor0 = __expf(rM0 - nM0), cor1 = __expf(rM1 - nM1);
        rM0 = nM0; rM1 = nM1;

        float sum0 = 0.f, sum1 = 0.f;
        uint32_t pH01[8], pH23[8], pL01[8], pL23[8];
#pragma unroll
        for (int nt = 0; nt < 8; nt++) {
            float p0 = __expf(sacc[nt][0] - nM0);
            float p1 = __expf(sacc[nt][1] - nM0);
            float p2 = __expf(sacc[nt][2] - nM1);
            float p3 = __expf(sacc[nt][3] - nM1);
            sum0 += p0 + p1; sum1 += p2 + p3;
            __nv_bfloat16 h0 = __float2bfloat16(p0), h1 = __float2bfloat16(p1);
            __nv_bfloat16 h2 = __float2bfloat16(p2), h3 = __float2bfloat16(p3);
            pH01[nt] = pack_bf2(h0, h1);
            pH23[nt] = pack_bf2(h2, h3);
            pL01[nt] = pack_bf2(__float2bfloat16(p0 - __bfloat162float(h0)),
                                __float2bfloat16(p1 - __bfloat162float(h1)));
            pL23[nt] = pack_bf2(__float2bfloat16(p2 - __bfloat162float(h2)),
                                __float2bfloat16(p3 - __bfloat162float(h3)));
        }
        sum0 += __shfl_xor_sync(0xffffffffu, sum0, 1);
        sum0 += __shfl_xor_sync(0xffffffffu, sum0, 2);
        sum1 += __shfl_xor_sync(0xffffffffu, sum1, 1);
        sum1 += __shfl_xor_sync(0xffffffffu, sum1, 2);
        rL0 = rL0 * cor0 + sum0;
        rL1 = rL1 * cor1 + sum1;

#pragma unroll
        for (int dt = 0; dt < 16; dt++) {
            oacc[dt][0] *= cor0; oacc[dt][1] *= cor0;
            oacc[dt][2] *= cor1; oacc[dt][3] *= cor1;
        }

#pragma unroll
        for (int k2 = 0; k2 < 4; k2++) {
            uint32_t aH[4] = {pH01[2 * k2], pH23[2 * k2], pH01[2 * k2 + 1], pH23[2 * k2 + 1]};
            uint32_t aL[4] = {pL01[2 * k2], pL23[2 * k2], pL01[2 * k2 + 1], pL23[2 * k2 + 1]};
            int krow = k2 * 16 + ((lane >> 3) & 1) * 8 + (lane & 7);
#pragma unroll
            for (int dg = 0; dg < 8; dg++) {
                int dcol = dg * 16 + (lane >> 4) * 8;
                uint32_t off = ASW((uint32_t)(krow * 256 + dcol * 2));
                uint32_t vh4[4], vl4[4];
                ldsm4t(vh4, sVh + off);
                ldsm4t(vl4, sVl + off);
                mma_bf16(oacc[dg * 2], aH, vh4);
                mma_bf16(oacc[dg * 2], aH, vl4);
                mma_bf16(oacc[dg * 2], aL, vh4);
                mma_bf16(oacc[dg * 2 + 1], aH, vh4 + 2);
                mma_bf16(oacc[dg * 2 + 1], aH, vl4 + 2);
                mma_bf16(oacc[dg * 2 + 1], aL, vh4 + 2);
            }
        }
        __syncthreads();
        if (kt + 2 < nkt) load_kv(kt + 2, s);
    }

    // ---- normalize + split + store bf16 hi/lo y ----
    float il0 = 1.f / rL0, il1 = 1.f / rL1;
    size_t row0 = ((size_t)b * TT + r0g) * DM + h * DH;
    size_t row1 = row0 + (size_t)8 * DM;
#pragma unroll
    for (int dt = 0; dt < 16; dt++) {
        int c = dt * 8 + (lane & 3) * 2;
        float v0 = oacc[dt][0] * il0, v1 = oacc[dt][1] * il0;
        float v2 = oacc[dt][2] * il1, v3 = oacc[dt][3] * il1;
        __nv_bfloat16 h0 = __float2bfloat16(v0), h1 = __float2bfloat16(v1);
        __nv_bfloat16 h2 = __float2bfloat16(v2), h3 = __float2bfloat16(v3);
        *(uint32_t*)(g_yh + row0 + c) = pack_bf2(h0, h1);
        *(uint32_t*)(g_yh + row1 + c) = pack_bf2(h2, h3);
        *(uint32_t*)(g_yl + row0 + c) = pack_bf2(__float2bfloat16(v0 - __bfloat162float(h0)),
                                                 __float2bfloat16(v1 - __bfloat162float(h1)));
        *(uint32_t*)(g_yl + row1 + c) = pack_bf2(__float2bfloat16(v2 - __bfloat162float(h2)),
                                                 __float2bfloat16(v3 - __bfloat162float(h3)));
    }
}

// ======================================================================
extern "C" void kernel_launch(void* const* d_in, const int* in_sizes, int n_in,
                              void* d_out, int out_size)
{
    const float* x   = (const float*)d_in[0];
    const float* Wq  = (const float*)d_in[1];
    const float* Wkv = (const float*)d_in[2];
    const float* Wo  = (const float*)d_in[3];
    float* out = (float*)d_out;

    __nv_bfloat16 *xh, *xl, *wqh, *wql, *wkh, *wkl, *woh, *wol, *yh, *yl;
    cudaGetSymbolAddress((void**)&xh,  g_xh);  cudaGetSymbolAddress((void**)&xl,  g_xl);
    cudaGetSymbolAddress((void**)&wqh, g_wqh); cudaGetSymbolAddress((void**)&wql, g_wql);
    cudaGetSymbolAddress((void**)&wkh, g_wkh); cudaGetSymbolAddress((void**)&wkl, g_wkl);
    cudaGetSymbolAddress((void**)&woh, g_woh); cudaGetSymbolAddress((void**)&wol, g_wol);
    cudaGetSymbolAddress((void**)&yh,  g_yh);  cudaGetSymbolAddress((void**)&yl,  g_yl);

    cudaFuncSetAttribute(gemm_mma512, cudaFuncAttributeMaxDynamicSharedMemorySize, GEMM_SMEM);
    cudaFuncSetAttribute(gemm_qkv,    cudaFuncAttributeMaxDynamicSharedMemorySize, GEMM_SMEM);
    cudaFuncSetAttribute(attn_mma,    cudaFuncAttributeMaxDynamicSharedMemorySize, ATTN_SMEM);

    // 0) fp32 -> bf16 hi/lo splits (x, then all weights fused)
    conv_split<<<(BT * DM + 255) / 256, 256>>>(x, xh, xl, BT * DM);
    {
        int n1 = NQ * DM, n2 = NKV * DM, n3 = DM * DM;
        conv_w3<<<(n1 + n2 + n3 + 255) / 256, 256>>>(
            Wq, wqh, wql, n1, Wkv, wkh, wkl, n2, Wo, woh, wol, n3);
    }
    // 1) fused ab_q / ab_kv projections (one launch, 384 CTAs)
    {
        dim3 g(QTILES + 5, BT / 128);
        gemm_qkv<<<g, 512, GEMM_SMEM>>>(xh, xl);
    }
    // 2) q,k,v (+rotary) -> bf16 hi/lo
    qkv_kernel<<<BT, 128>>>();
    // 3) causal attention (tensor cores) -> yh/yl directly
    {
        dim3 g(TT / 128, NH, NB);
        attn_mma<<<g, 256, ATTN_SMEM>>>();
    }
    // 4) out = y @ W_o^T (4096 x 2048)
    {
        dim3 g(DM / 128, BT / 128);
        gemm_mma512<<<g, 512, GEMM_SMEM>>>(yh, yl, woh, wol, out, DM, DM);
    }
}